// round 2
// baseline (speedup 1.0000x reference)
#include <cuda_runtime.h>
#include <math.h>

#define NN 50000
#define EE 800000
#define DD 128
#define HH 8

// Scratch (static device arrays — no allocation)
__device__ float g_Q[NN * DD];
__device__ float g_K[NN * DD];
__device__ float g_V[NN * DD];
__device__ float g_wV[NN * DD];
__device__ float g_z[NN * HH];
__device__ float g_h[NN * DD];
__device__ float g_t[NN * DD];

// ---------------------------------------------------------------------------
// Zero the accumulators (d_out/scratch poisoned; atomics need zeros)
// ---------------------------------------------------------------------------
__global__ void zero_kernel() {
    int idx = blockIdx.x * 256 + threadIdx.x;
    float4 zf = make_float4(0.f, 0.f, 0.f, 0.f);
    if (idx < NN * DD / 4) reinterpret_cast<float4*>(g_wV)[idx] = zf;
    if (idx < NN * HH)     g_z[idx] = 0.f;
}

// ---------------------------------------------------------------------------
// Fused QKV GEMM: out = x @ W + b for W in {Wq, Wk, Wv} (blockIdx.y selects)
// Block computes 64 rows x 128 cols. smem: x tile 32KB + full W 64KB = 96KB.
// ---------------------------------------------------------------------------
__global__ void qkv_gemm(const float* __restrict__ x,
                         const float* __restrict__ Wq, const float* __restrict__ bq,
                         const float* __restrict__ Wk, const float* __restrict__ bk,
                         const float* __restrict__ Wv, const float* __restrict__ bv) {
    extern __shared__ float sm[];
    float*  xs  = sm;                 // [64][128]
    float*  ws  = sm + 64 * DD;       // [128][128]
    float4* xs4 = reinterpret_cast<float4*>(xs);
    float4* ws4 = reinterpret_cast<float4*>(ws);

    const float* W; const float* b; float* out;
    if (blockIdx.y == 0)      { W = Wq; b = bq; out = g_Q; }
    else if (blockIdx.y == 1) { W = Wk; b = bk; out = g_K; }
    else                      { W = Wv; b = bv; out = g_V; }

    int row0 = blockIdx.x * 64;
    int t = threadIdx.x;

    const float4* xg = reinterpret_cast<const float4*>(x + (size_t)row0 * DD);
    int maxv = min(64, NN - row0) * (DD / 4);
    for (int i = t; i < 64 * (DD / 4); i += 256)
        xs4[i] = (i < maxv) ? xg[i] : make_float4(0.f, 0.f, 0.f, 0.f);

    const float4* wg = reinterpret_cast<const float4*>(W);
    for (int i = t; i < DD * (DD / 4); i += 256)
        ws4[i] = wg[i];
    __syncthreads();

    int tx = t & 31;   // col group: cols 4*tx..4*tx+3
    int ty = t >> 5;   // row group: rows ty*8..ty*8+7

    float acc[8][4];
#pragma unroll
    for (int r = 0; r < 8; r++)
#pragma unroll
        for (int c = 0; c < 4; c++) acc[r][c] = 0.f;

#pragma unroll 4
    for (int k = 0; k < DD; k++) {
        float4 w = ws4[k * (DD / 4) + tx];
#pragma unroll
        for (int r = 0; r < 8; r++) {
            float xr = xs[(ty * 8 + r) * DD + k];
            acc[r][0] = fmaf(xr, w.x, acc[r][0]);
            acc[r][1] = fmaf(xr, w.y, acc[r][1]);
            acc[r][2] = fmaf(xr, w.z, acc[r][2]);
            acc[r][3] = fmaf(xr, w.w, acc[r][3]);
        }
    }

    float4 bb = reinterpret_cast<const float4*>(b)[tx];
#pragma unroll
    for (int r = 0; r < 8; r++) {
        int row = row0 + ty * 8 + r;
        if (row < NN) {
            float4 o;
            o.x = acc[r][0] + bb.x;
            o.y = acc[r][1] + bb.y;
            o.z = acc[r][2] + bb.z;
            o.w = acc[r][3] + bb.w;
            reinterpret_cast<float4*>(out + (size_t)row * DD)[tx] = o;
        }
    }
}

// ---------------------------------------------------------------------------
// Edge kernel: one warp per edge.
// lane l handles dims [4l, 4l+4) => head = l>>2, 4-lane shfl reduce per head.
// score = exp(clip(K[src].Q[dst]/4, -5, 5)); scatter wV[dst]+=V[src]*score,
// z[dst,h]+=score via red.global vector atomics.
// ---------------------------------------------------------------------------
__global__ void edge_kernel(const int* __restrict__ src, const int* __restrict__ dst) {
    int warp = (blockIdx.x * blockDim.x + threadIdx.x) >> 5;
    int lane = threadIdx.x & 31;
    if (warp >= EE) return;

    int s = __ldg(src + warp);
    int d = __ldg(dst + warp);

    // issue all gathers up front for MLP
    float4 kv = reinterpret_cast<const float4*>(g_K + (size_t)s * DD)[lane];
    float4 qv = reinterpret_cast<const float4*>(g_Q + (size_t)d * DD)[lane];
    float4 vv = reinterpret_cast<const float4*>(g_V + (size_t)s * DD)[lane];

    float p = kv.x * qv.x + kv.y * qv.y + kv.z * qv.z + kv.w * qv.w;
    p += __shfl_xor_sync(0xffffffffu, p, 1);
    p += __shfl_xor_sync(0xffffffffu, p, 2);   // sum over the 4 lanes of this head

    float sc = __expf(fminf(fmaxf(p * 0.25f, -5.f), 5.f));

    float4* wptr = reinterpret_cast<float4*>(g_wV + (size_t)d * DD) + lane;
    asm volatile("red.global.add.v4.f32 [%0], {%1, %2, %3, %4};"
                 :: "l"(wptr), "f"(vv.x * sc), "f"(vv.y * sc),
                    "f"(vv.z * sc), "f"(vv.w * sc)
                 : "memory");
    if ((lane & 3) == 0)
        atomicAdd(g_z + (size_t)d * HH + (lane >> 2), sc);
}

// ---------------------------------------------------------------------------
// Norm kernel: one warp per node.
// attn = wV/(z+1e-3); h = LN1(x+attn); t = LN2(h). Stores h and t.
// ---------------------------------------------------------------------------
__global__ void norm_kernel(const float* __restrict__ x,
                            const float* __restrict__ gamma1, const float* __restrict__ beta1,
                            const float* __restrict__ gamma2, const float* __restrict__ beta2) {
    int node = (blockIdx.x * blockDim.x + threadIdx.x) >> 5;
    int lane = threadIdx.x & 31;
    if (node >= NN) return;

    float4 xv = reinterpret_cast<const float4*>(x + (size_t)node * DD)[lane];
    float4 wv = reinterpret_cast<const float4*>(g_wV + (size_t)node * DD)[lane];
    float rz = 1.f / (g_z[(size_t)node * HH + (lane >> 2)] + 1e-3f);

    float4 y;
    y.x = xv.x + wv.x * rz;
    y.y = xv.y + wv.y * rz;
    y.z = xv.z + wv.z * rz;
    y.w = xv.w + wv.w * rz;

    // --- LN1 ---
    float s  = y.x + y.y + y.z + y.w;
    float sq = y.x * y.x + y.y * y.y + y.z * y.z + y.w * y.w;
#pragma unroll
    for (int o = 16; o > 0; o >>= 1) {
        s  += __shfl_xor_sync(0xffffffffu, s,  o);
        sq += __shfl_xor_sync(0xffffffffu, sq, o);
    }
    float mu  = s * (1.f / DD);
    float var = sq * (1.f / DD) - mu * mu;
    float inv = rsqrtf(var + 1e-5f);

    float4 g1 = reinterpret_cast<const float4*>(gamma1)[lane];
    float4 b1 = reinterpret_cast<const float4*>(beta1)[lane];
    float4 h;
    h.x = (y.x - mu) * inv * g1.x + b1.x;
    h.y = (y.y - mu) * inv * g1.y + b1.y;
    h.z = (y.z - mu) * inv * g1.z + b1.z;
    h.w = (y.w - mu) * inv * g1.w + b1.w;
    reinterpret_cast<float4*>(g_h + (size_t)node * DD)[lane] = h;

    // --- LN2 ---
    float s2  = h.x + h.y + h.z + h.w;
    float sq2 = h.x * h.x + h.y * h.y + h.z * h.z + h.w * h.w;
#pragma unroll
    for (int o = 16; o > 0; o >>= 1) {
        s2  += __shfl_xor_sync(0xffffffffu, s2,  o);
        sq2 += __shfl_xor_sync(0xffffffffu, sq2, o);
    }
    float mu2  = s2 * (1.f / DD);
    float var2 = sq2 * (1.f / DD) - mu2 * mu2;
    float inv2 = rsqrtf(var2 + 1e-5f);

    float4 g2 = reinterpret_cast<const float4*>(gamma2)[lane];
    float4 b2 = reinterpret_cast<const float4*>(beta2)[lane];
    float4 tt;
    tt.x = (h.x - mu2) * inv2 * g2.x + b2.x;
    tt.y = (h.y - mu2) * inv2 * g2.y + b2.y;
    tt.z = (h.z - mu2) * inv2 * g2.z + b2.z;
    tt.w = (h.w - mu2) * inv2 * g2.w + b2.w;
    reinterpret_cast<float4*>(g_t + (size_t)node * DD)[lane] = tt;
}

// ---------------------------------------------------------------------------
// Output GEMM: out = h + relu(t @ Wo + bo)
// ---------------------------------------------------------------------------
__global__ void out_gemm(const float* __restrict__ Wo, const float* __restrict__ bo,
                         float* __restrict__ out) {
    extern __shared__ float sm[];
    float*  xs  = sm;
    float*  ws  = sm + 64 * DD;
    float4* xs4 = reinterpret_cast<float4*>(xs);
    float4* ws4 = reinterpret_cast<float4*>(ws);

    int row0 = blockIdx.x * 64;
    int t = threadIdx.x;

    const float4* xg = reinterpret_cast<const float4*>(g_t + (size_t)row0 * DD);
    int maxv = min(64, NN - row0) * (DD / 4);
    for (int i = t; i < 64 * (DD / 4); i += 256)
        xs4[i] = (i < maxv) ? xg[i] : make_float4(0.f, 0.f, 0.f, 0.f);

    const float4* wg = reinterpret_cast<const float4*>(Wo);
    for (int i = t; i < DD * (DD / 4); i += 256)
        ws4[i] = wg[i];
    __syncthreads();

    int tx = t & 31;
    int ty = t >> 5;

    float acc[8][4];
#pragma unroll
    for (int r = 0; r < 8; r++)
#pragma unroll
        for (int c = 0; c < 4; c++) acc[r][c] = 0.f;

#pragma unroll 4
    for (int k = 0; k < DD; k++) {
        float4 w = ws4[k * (DD / 4) + tx];
#pragma unroll
        for (int r = 0; r < 8; r++) {
            float xr = xs[(ty * 8 + r) * DD + k];
            acc[r][0] = fmaf(xr, w.x, acc[r][0]);
            acc[r][1] = fmaf(xr, w.y, acc[r][1]);
            acc[r][2] = fmaf(xr, w.z, acc[r][2]);
            acc[r][3] = fmaf(xr, w.w, acc[r][3]);
        }
    }

    float4 bb = reinterpret_cast<const float4*>(bo)[tx];
#pragma unroll
    for (int r = 0; r < 8; r++) {
        int row = row0 + ty * 8 + r;
        if (row < NN) {
            float4 hv = reinterpret_cast<const float4*>(g_h + (size_t)row * DD)[tx];
            float4 o;
            o.x = hv.x + fmaxf(acc[r][0] + bb.x, 0.f);
            o.y = hv.y + fmaxf(acc[r][1] + bb.y, 0.f);
            o.z = hv.z + fmaxf(acc[r][2] + bb.z, 0.f);
            o.w = hv.w + fmaxf(acc[r][3] + bb.w, 0.f);
            reinterpret_cast<float4*>(out + (size_t)row * DD)[tx] = o;
        }
    }
}

// ---------------------------------------------------------------------------
extern "C" void kernel_launch(void* const* d_in, const int* in_sizes, int n_in,
                              void* d_out, int out_size) {
    const float* x      = (const float*)d_in[0];
    const int*   src    = (const int*)  d_in[1];
    const int*   dst    = (const int*)  d_in[2];
    const float* Wq     = (const float*)d_in[3];
    const float* bq     = (const float*)d_in[4];
    const float* Wk     = (const float*)d_in[5];
    const float* bk     = (const float*)d_in[6];
    const float* Wv     = (const float*)d_in[7];
    const float* bv     = (const float*)d_in[8];
    const float* Wo     = (const float*)d_in[9];
    const float* bo     = (const float*)d_in[10];
    const float* gamma1 = (const float*)d_in[11];
    const float* beta1  = (const float*)d_in[12];
    const float* gamma2 = (const float*)d_in[13];
    const float* beta2  = (const float*)d_in[14];
    float* out = (float*)d_out;

    const int smem = (64 * DD + DD * DD) * sizeof(float);  // 96KB
    cudaFuncSetAttribute(qkv_gemm, cudaFuncAttributeMaxDynamicSharedMemorySize, smem);
    cudaFuncSetAttribute(out_gemm, cudaFuncAttributeMaxDynamicSharedMemorySize, smem);

    // zero accumulators
    zero_kernel<<<(NN * DD / 4 + 255) / 256, 256>>>();

    // QKV projections
    dim3 qkv_grid((NN + 63) / 64, 3);
    qkv_gemm<<<qkv_grid, 256, smem>>>(x, Wq, bq, Wk, bk, Wv, bv);

    // edge scores + scatter
    edge_kernel<<<EE / 8, 256>>>(src, dst);

    // attn normalize + LN1 + LN2
    norm_kernel<<<(NN + 7) / 8, 256>>>(x, gamma1, beta1, gamma2, beta2);

    // output projection + relu + residual
    out_gemm<<<(NN + 63) / 64, 256, smem>>>(Wo, bo, out);
}

// round 8
// speedup vs baseline: 1.1297x; 1.1297x over previous
#include <cuda_runtime.h>
#include <cuda_bf16.h>
#include <math.h>
#include <stdint.h>

#define NN 50000
#define EE 800000
#define DD 128
#define HH 8

// ---------------- scratch (static device arrays, no allocation) -------------
__device__ float g_Q[NN * DD];
__device__ float g_K[NN * DD];
__device__ float g_V[NN * DD];
__device__ float g_wV[NN * DD];
__device__ float g_z[NN * HH];
__device__ float g_h[NN * DD];
// bf16 hi/lo splits of activations, packed bf16x2 (pair p = cols 2p, 2p+1)
__device__ unsigned int g_xhi[NN * 64];
__device__ unsigned int g_xlo[NN * 64];
__device__ unsigned int g_thi[NN * 64];
__device__ unsigned int g_tlo[NN * 64];
// W pre-baked into m16n8k16 B-fragment layout: [matrix][(kk*16+nn)*32 + lane]
__device__ uint2 g_wfh[4][4096];
__device__ uint2 g_wfl[4][4096];

// ---------------- helpers ---------------------------------------------------
__device__ __forceinline__ unsigned int smem_u32(const void* p) {
    unsigned int a;
    asm("{ .reg .u64 t; cvta.to.shared.u64 t, %1; cvt.u32.u64 %0, t; }" : "=r"(a) : "l"(p));
    return a;
}

__device__ __forceinline__ unsigned int pack_bf(float a, float b) {
    __nv_bfloat162 t = __floats2bfloat162_rn(a, b);
    return *reinterpret_cast<unsigned int*>(&t);
}

#define MMA_BF16(c, a, b0v, b1v)                                               \
    asm volatile("mma.sync.aligned.m16n8k16.row.col.f32.bf16.bf16.f32 "        \
                 "{%0,%1,%2,%3}, {%4,%5,%6,%7}, {%8,%9}, {%0,%1,%2,%3};"       \
                 : "+f"((c)[0]), "+f"((c)[1]), "+f"((c)[2]), "+f"((c)[3])      \
                 : "r"((a)[0]), "r"((a)[1]), "r"((a)[2]), "r"((a)[3]),         \
                   "r"(b0v), "r"(b1v))

#define LDMATRIX_X4(r, addr)                                                   \
    asm volatile("ldmatrix.sync.aligned.m8n8.x4.shared.b16 {%0,%1,%2,%3}, [%4];" \
                 : "=r"((r)[0]), "=r"((r)[1]), "=r"((r)[2]), "=r"((r)[3])      \
                 : "r"(addr))

// ---------------------------------------------------------------------------
// Zero accumulators
// ---------------------------------------------------------------------------
__global__ void zero_kernel() {
    int idx = blockIdx.x * 256 + threadIdx.x;
    float4 zf = make_float4(0.f, 0.f, 0.f, 0.f);
    if (idx < NN * DD / 4) reinterpret_cast<float4*>(g_wV)[idx] = zf;
    if (idx < NN * HH)     g_z[idx] = 0.f;
}

// ---------------------------------------------------------------------------
// Convert x -> bf16 hi/lo pairs
// ---------------------------------------------------------------------------
__global__ void convert_x(const float* __restrict__ x) {
    int i = blockIdx.x * 256 + threadIdx.x;
    if (i >= NN * 64) return;
    float2 v = reinterpret_cast<const float2*>(x)[i];
    __nv_bfloat162 hp = __floats2bfloat162_rn(v.x, v.y);
    float l0 = v.x - __bfloat162float(hp.x);
    float l1 = v.y - __bfloat162float(hp.y);
    g_xhi[i] = *reinterpret_cast<unsigned int*>(&hp);
    g_xlo[i] = pack_bf(l0, l1);
}

// ---------------------------------------------------------------------------
// Bake W (4 matrices) into mma.sync B-fragment layout (hi + lo splits).
// Fragment (kk,nn,lane): g=lane>>2, tig=lane&3
//   b0 = {W[kk*16+2tig][nn*8+g], W[kk*16+2tig+1][nn*8+g]}
//   b1 = {W[kk*16+2tig+8][..],   W[kk*16+2tig+9][..]}
// ---------------------------------------------------------------------------
__global__ void convert_w(const float* __restrict__ Wq, const float* __restrict__ Wk,
                          const float* __restrict__ Wv, const float* __restrict__ Wo) {
    int m = blockIdx.y;
    const float* W = (m == 0) ? Wq : (m == 1) ? Wk : (m == 2) ? Wv : Wo;
    int i = blockIdx.x * 256 + threadIdx.x;
    if (i >= 4096) return;
    int lane = i & 31, nn = (i >> 5) & 15, kk = i >> 9;
    int g = lane >> 2, tig = lane & 3;
    int k0 = kk * 16 + 2 * tig;
    int col = nn * 8 + g;

    float w00 = W[(k0)     * 128 + col];
    float w01 = W[(k0 + 1) * 128 + col];
    float w10 = W[(k0 + 8) * 128 + col];
    float w11 = W[(k0 + 9) * 128 + col];

    __nv_bfloat16 h00 = __float2bfloat16_rn(w00);
    __nv_bfloat16 h01 = __float2bfloat16_rn(w01);
    __nv_bfloat16 h10 = __float2bfloat16_rn(w10);
    __nv_bfloat16 h11 = __float2bfloat16_rn(w11);

    g_wfh[m][i] = make_uint2(pack_bf(w00, w01), pack_bf(w10, w11));
    g_wfl[m][i] = make_uint2(
        pack_bf(w00 - __bfloat162float(h00), w01 - __bfloat162float(h01)),
        pack_bf(w10 - __bfloat162float(h10), w11 - __bfloat162float(h11)));
}

// ---------------------------------------------------------------------------
// mma.sync GEMM: D[128 rows, 128 cols] = A @ W, bf16x3 split, fp32 accum.
// A selected INSIDE the kernel (device symbols are not valid host args!):
//   a_is_t=0: A = x split;  a_is_t=1: A = t split (LN2 output)
// qkv mode (is_out=0): blockIdx.y selects Wq/Wk/Wv -> g_Q/K/V
// out mode (is_out=1): W = Wo, out = g_h + relu(D + bo)
// ---------------------------------------------------------------------------
__global__ void __launch_bounds__(256)
mma_gemm(int a_is_t, int w_base, const float* __restrict__ b0,
         const float* __restrict__ b1, const float* __restrict__ b2,
         float* __restrict__ dout, int is_out) {
    extern __shared__ char smem[];
    // A tiles: 128 rows x 136 bf16 stride (272B rows -> conflict-free ldmatrix)
    const int A_STRIDE_B = 272;
    const int OFF_LO = 128 * A_STRIDE_B;   // 34816
    int t = threadIdx.x, warp = t >> 5, lane = t & 31;
    int sel = blockIdx.y;
    int row0 = blockIdx.x * 128;

    const unsigned int* __restrict__ Ahi = a_is_t ? g_thi : g_xhi;
    const unsigned int* __restrict__ Alo = a_is_t ? g_tlo : g_xlo;
    const uint2* wfh = g_wfh[w_base + sel];
    const uint2* wfl = g_wfl[w_base + sel];
    const float* bias = is_out ? b0 : (sel == 0 ? b0 : sel == 1 ? b1 : b2);
    float* outp = is_out ? dout : (sel == 0 ? g_Q : sel == 1 ? g_K : g_V);

    // fill A hi/lo smem tiles
    for (int i = t; i < 8192; i += 256) {
        int row = i >> 6, p = i & 63;
        int grow = row0 + row;
        unsigned int vh = 0, vl = 0;
        if (grow < NN) { vh = Ahi[grow * 64 + p]; vl = Alo[grow * 64 + p]; }
        int off = row * A_STRIDE_B + p * 4;
        *reinterpret_cast<unsigned int*>(smem + off)          = vh;
        *reinterpret_cast<unsigned int*>(smem + OFF_LO + off) = vl;
    }
    __syncthreads();

    // ldmatrix source address for this lane
    int rowsel = (lane & 7) | (((lane >> 3) & 1) << 3);  // 0..15
    int colblk = lane >> 4;                              // 0/1 -> k +0/+8
    unsigned int sb = smem_u32(smem);
    unsigned int a_addr = sb + (warp * 16 + rowsel) * A_STRIDE_B + colblk * 16;

    float acc[16][4];
#pragma unroll
    for (int nn = 0; nn < 16; nn++)
#pragma unroll
        for (int c = 0; c < 4; c++) acc[nn][c] = 0.f;

#pragma unroll
    for (int kk = 0; kk < 8; kk++) {
        unsigned int a_hi[4], a_lo[4];
        LDMATRIX_X4(a_hi, a_addr + kk * 32);
        LDMATRIX_X4(a_lo, a_addr + OFF_LO + kk * 32);
        const uint2* wh = wfh + kk * 16 * 32 + lane;
        const uint2* wl = wfl + kk * 16 * 32 + lane;
#pragma unroll
        for (int nn = 0; nn < 16; nn++) {
            uint2 bh = __ldg(wh + nn * 32);
            uint2 bl = __ldg(wl + nn * 32);
            MMA_BF16(acc[nn], a_hi, bh.x, bh.y);
            MMA_BF16(acc[nn], a_hi, bl.x, bl.y);
            MMA_BF16(acc[nn], a_lo, bh.x, bh.y);
        }
    }

    // epilogue: lane g holds rows g/g+8, cols 2tig..2tig+1 per ntile
    int g = lane >> 2, tig = lane & 3;
    int r_lo = row0 + warp * 16 + g;
    int r_hi = r_lo + 8;
#pragma unroll
    for (int nn = 0; nn < 16; nn++) {
        int col = nn * 8 + 2 * tig;
        float2 bb = *reinterpret_cast<const float2*>(bias + col);
        if (r_lo < NN) {
            float2 o;
            if (is_out) {
                float2 hv = *reinterpret_cast<const float2*>(g_h + (size_t)r_lo * DD + col);
                o.x = hv.x + fmaxf(acc[nn][0] + bb.x, 0.f);
                o.y = hv.y + fmaxf(acc[nn][1] + bb.y, 0.f);
            } else {
                o.x = acc[nn][0] + bb.x;
                o.y = acc[nn][1] + bb.y;
            }
            *reinterpret_cast<float2*>(outp + (size_t)r_lo * DD + col) = o;
        }
        if (r_hi < NN) {
            float2 o;
            if (is_out) {
                float2 hv = *reinterpret_cast<const float2*>(g_h + (size_t)r_hi * DD + col);
                o.x = hv.x + fmaxf(acc[nn][2] + bb.x, 0.f);
                o.y = hv.y + fmaxf(acc[nn][3] + bb.y, 0.f);
            } else {
                o.x = acc[nn][2] + bb.x;
                o.y = acc[nn][3] + bb.y;
            }
            *reinterpret_cast<float2*>(outp + (size_t)r_hi * DD + col) = o;
        }
    }
}

// ---------------------------------------------------------------------------
// Edge kernel: one warp per edge
// ---------------------------------------------------------------------------
__global__ void edge_kernel(const int* __restrict__ src, const int* __restrict__ dst) {
    int warp = (blockIdx.x * blockDim.x + threadIdx.x) >> 5;
    int lane = threadIdx.x & 31;
    if (warp >= EE) return;

    int s = __ldg(src + warp);
    int d = __ldg(dst + warp);

    float4 kv = reinterpret_cast<const float4*>(g_K + (size_t)s * DD)[lane];
    float4 qv = reinterpret_cast<const float4*>(g_Q + (size_t)d * DD)[lane];
    float4 vv = reinterpret_cast<const float4*>(g_V + (size_t)s * DD)[lane];

    float p = kv.x * qv.x + kv.y * qv.y + kv.z * qv.z + kv.w * qv.w;
    p += __shfl_xor_sync(0xffffffffu, p, 1);
    p += __shfl_xor_sync(0xffffffffu, p, 2);

    float sc = __expf(fminf(fmaxf(p * 0.25f, -5.f), 5.f));

    float4* wptr = reinterpret_cast<float4*>(g_wV + (size_t)d * DD) + lane;
    asm volatile("red.global.add.v4.f32 [%0], {%1, %2, %3, %4};"
                 :: "l"(wptr), "f"(vv.x * sc), "f"(vv.y * sc),
                    "f"(vv.z * sc), "f"(vv.w * sc)
                 : "memory");
    if ((lane & 3) == 0)
        atomicAdd(g_z + (size_t)d * HH + (lane >> 2), sc);
}

// ---------------------------------------------------------------------------
// Norm kernel: attn normalize + LN1 -> g_h, LN2 -> bf16 split (g_thi/g_tlo)
// ---------------------------------------------------------------------------
__global__ void norm_kernel(const float* __restrict__ x,
                            const float* __restrict__ gamma1, const float* __restrict__ beta1,
                            const float* __restrict__ gamma2, const float* __restrict__ beta2) {
    int node = (blockIdx.x * blockDim.x + threadIdx.x) >> 5;
    int lane = threadIdx.x & 31;
    if (node >= NN) return;

    float4 xv = reinterpret_cast<const float4*>(x + (size_t)node * DD)[lane];
    float4 wv = reinterpret_cast<const float4*>(g_wV + (size_t)node * DD)[lane];
    float rz = 1.f / (g_z[(size_t)node * HH + (lane >> 2)] + 1e-3f);

    float4 y;
    y.x = xv.x + wv.x * rz;
    y.y = xv.y + wv.y * rz;
    y.z = xv.z + wv.z * rz;
    y.w = xv.w + wv.w * rz;

    float s  = y.x + y.y + y.z + y.w;
    float sq = y.x * y.x + y.y * y.y + y.z * y.z + y.w * y.w;
#pragma unroll
    for (int o = 16; o > 0; o >>= 1) {
        s  += __shfl_xor_sync(0xffffffffu, s,  o);
        sq += __shfl_xor_sync(0xffffffffu, sq, o);
    }
    float mu  = s * (1.f / DD);
    float var = sq * (1.f / DD) - mu * mu;
    float inv = rsqrtf(var + 1e-5f);

    float4 g1 = reinterpret_cast<const float4*>(gamma1)[lane];
    float4 b1 = reinterpret_cast<const float4*>(beta1)[lane];
    float4 h;
    h.x = (y.x - mu) * inv * g1.x + b1.x;
    h.y = (y.y - mu) * inv * g1.y + b1.y;
    h.z = (y.z - mu) * inv * g1.z + b1.z;
    h.w = (y.w - mu) * inv * g1.w + b1.w;
    reinterpret_cast<float4*>(g_h + (size_t)node * DD)[lane] = h;

    float s2  = h.x + h.y + h.z + h.w;
    float sq2 = h.x * h.x + h.y * h.y + h.z * h.z + h.w * h.w;
#pragma unroll
    for (int o = 16; o > 0; o >>= 1) {
        s2  += __shfl_xor_sync(0xffffffffu, s2,  o);
        sq2 += __shfl_xor_sync(0xffffffffu, sq2, o);
    }
    float mu2  = s2 * (1.f / DD);
    float var2 = sq2 * (1.f / DD) - mu2 * mu2;
    float inv2 = rsqrtf(var2 + 1e-5f);

    float4 g2 = reinterpret_cast<const float4*>(gamma2)[lane];
    float4 b2 = reinterpret_cast<const float4*>(beta2)[lane];
    float4 tt;
    tt.x = (h.x - mu2) * inv2 * g2.x + b2.x;
    tt.y = (h.y - mu2) * inv2 * g2.y + b2.y;
    tt.z = (h.z - mu2) * inv2 * g2.z + b2.z;
    tt.w = (h.w - mu2) * inv2 * g2.w + b2.w;

    __nv_bfloat162 h01 = __floats2bfloat162_rn(tt.x, tt.y);
    __nv_bfloat162 h23 = __floats2bfloat162_rn(tt.z, tt.w);
    float l0 = tt.x - __bfloat162float(h01.x);
    float l1 = tt.y - __bfloat162float(h01.y);
    float l2 = tt.z - __bfloat162float(h23.x);
    float l3 = tt.w - __bfloat162float(h23.y);
    int base = node * 64 + lane * 2;
    g_thi[base]     = *reinterpret_cast<unsigned int*>(&h01);
    g_thi[base + 1] = *reinterpret_cast<unsigned int*>(&h23);
    g_tlo[base]     = pack_bf(l0, l1);
    g_tlo[base + 1] = pack_bf(l2, l3);
}

// ---------------------------------------------------------------------------
extern "C" void kernel_launch(void* const* d_in, const int* in_sizes, int n_in,
                              void* d_out, int out_size) {
    const float* x      = (const float*)d_in[0];
    const int*   src    = (const int*)  d_in[1];
    const int*   dst    = (const int*)  d_in[2];
    const float* Wq     = (const float*)d_in[3];
    const float* bq     = (const float*)d_in[4];
    const float* Wk     = (const float*)d_in[5];
    const float* bk     = (const float*)d_in[6];
    const float* Wv     = (const float*)d_in[7];
    const float* bv     = (const float*)d_in[8];
    const float* Wo     = (const float*)d_in[9];
    const float* bo     = (const float*)d_in[10];
    const float* gamma1 = (const float*)d_in[11];
    const float* beta1  = (const float*)d_in[12];
    const float* gamma2 = (const float*)d_in[13];
    const float* beta2  = (const float*)d_in[14];
    float* out = (float*)d_out;

    const int MMA_SMEM = 2 * 128 * 272;  // 69632 B
    cudaFuncSetAttribute(mma_gemm, cudaFuncAttributeMaxDynamicSharedMemorySize, MMA_SMEM);

    // zero accumulators
    zero_kernel<<<(NN * DD / 4 + 255) / 256, 256>>>();

    // bf16 splits + W fragment bake
    convert_x<<<(NN * 64 + 255) / 256, 256>>>(x);
    convert_w<<<dim3(16, 4), 256>>>(Wq, Wk, Wv, Wo);

    // QKV projections (mma.sync bf16x3); A = x split (selected in-kernel)
    dim3 qkv_grid((NN + 127) / 128, 3);
    mma_gemm<<<qkv_grid, 256, MMA_SMEM>>>(0, 0, bq, bk, bv, nullptr, 0);

    // edge scores + scatter
    edge_kernel<<<EE / 8, 256>>>(src, dst);

    // attn normalize + LN1 + LN2(+split)
    norm_kernel<<<(NN + 7) / 8, 256>>>(x, gamma1, beta1, gamma2, beta2);

    // output projection + relu + residual; A = t split (selected in-kernel)
    mma_gemm<<<dim3((NN + 127) / 128, 1), 256, MMA_SMEM>>>(1, 3, bo, bo, bo, out, 1);
}

// round 9
// speedup vs baseline: 1.3290x; 1.1764x over previous
#include <cuda_runtime.h>
#include <cuda_bf16.h>
#include <math.h>
#include <stdint.h>

#define NN 50000
#define EE 800000
#define DD 128
#define HH 8

// ---------------- scratch (static device arrays, no allocation) -------------
__device__ float g_Q[NN * DD];
__device__ float g_K[NN * DD];
__device__ float g_V[NN * DD];
__device__ float g_wV[NN * DD];
__device__ float g_z[NN * HH];
__device__ float g_h[NN * DD];
// bf16 hi/lo splits of activations, packed bf16x2 (pair p = cols 2p, 2p+1)
__device__ unsigned int g_xhi[NN * 64];
__device__ unsigned int g_xlo[NN * 64];
__device__ unsigned int g_thi[NN * 64];
__device__ unsigned int g_tlo[NN * 64];
// W pre-baked into m16n8k16 B-fragment layout: [matrix][(kk*16+nn)*32 + lane]
__device__ uint2 g_wfh[4][4096];
__device__ uint2 g_wfl[4][4096];

// ---------------- helpers ---------------------------------------------------
__device__ __forceinline__ unsigned int smem_u32(const void* p) {
    unsigned int a;
    asm("{ .reg .u64 t; cvta.to.shared.u64 t, %1; cvt.u32.u64 %0, t; }" : "=r"(a) : "l"(p));
    return a;
}

__device__ __forceinline__ unsigned int pack_bf(float a, float b) {
    __nv_bfloat162 t = __floats2bfloat162_rn(a, b);
    return *reinterpret_cast<unsigned int*>(&t);
}

#define MMA_BF16(c, a, b0v, b1v)                                               \
    asm volatile("mma.sync.aligned.m16n8k16.row.col.f32.bf16.bf16.f32 "        \
                 "{%0,%1,%2,%3}, {%4,%5,%6,%7}, {%8,%9}, {%0,%1,%2,%3};"       \
                 : "+f"((c)[0]), "+f"((c)[1]), "+f"((c)[2]), "+f"((c)[3])      \
                 : "r"((a)[0]), "r"((a)[1]), "r"((a)[2]), "r"((a)[3]),         \
                   "r"(b0v), "r"(b1v))

#define LDMATRIX_X4(r, addr)                                                   \
    asm volatile("ldmatrix.sync.aligned.m8n8.x4.shared.b16 {%0,%1,%2,%3}, [%4];" \
                 : "=r"((r)[0]), "=r"((r)[1]), "=r"((r)[2]), "=r"((r)[3])      \
                 : "r"(addr))

// ---------------------------------------------------------------------------
// Zero accumulators
// ---------------------------------------------------------------------------
__global__ void zero_kernel() {
    int idx = blockIdx.x * 256 + threadIdx.x;
    float4 zf = make_float4(0.f, 0.f, 0.f, 0.f);
    if (idx < NN * DD / 4) reinterpret_cast<float4*>(g_wV)[idx] = zf;
    if (idx < NN * HH)     g_z[idx] = 0.f;
}

// ---------------------------------------------------------------------------
// Convert x -> bf16 hi/lo pairs
// ---------------------------------------------------------------------------
__global__ void convert_x(const float* __restrict__ x) {
    int i = blockIdx.x * 256 + threadIdx.x;
    if (i >= NN * 64) return;
    float2 v = reinterpret_cast<const float2*>(x)[i];
    __nv_bfloat162 hp = __floats2bfloat162_rn(v.x, v.y);
    float l0 = v.x - __bfloat162float(hp.x);
    float l1 = v.y - __bfloat162float(hp.y);
    g_xhi[i] = *reinterpret_cast<unsigned int*>(&hp);
    g_xlo[i] = pack_bf(l0, l1);
}

// ---------------------------------------------------------------------------
// Bake W (4 matrices) into mma.sync B-fragment layout (hi + lo splits).
// ---------------------------------------------------------------------------
__global__ void convert_w(const float* __restrict__ Wq, const float* __restrict__ Wk,
                          const float* __restrict__ Wv, const float* __restrict__ Wo) {
    int m = blockIdx.y;
    const float* W = (m == 0) ? Wq : (m == 1) ? Wk : (m == 2) ? Wv : Wo;
    int i = blockIdx.x * 256 + threadIdx.x;
    if (i >= 4096) return;
    int lane = i & 31, nn = (i >> 5) & 15, kk = i >> 9;
    int g = lane >> 2, tig = lane & 3;
    int k0 = kk * 16 + 2 * tig;
    int col = nn * 8 + g;

    float w00 = W[(k0)     * 128 + col];
    float w01 = W[(k0 + 1) * 128 + col];
    float w10 = W[(k0 + 8) * 128 + col];
    float w11 = W[(k0 + 9) * 128 + col];

    __nv_bfloat16 h00 = __float2bfloat16_rn(w00);
    __nv_bfloat16 h01 = __float2bfloat16_rn(w01);
    __nv_bfloat16 h10 = __float2bfloat16_rn(w10);
    __nv_bfloat16 h11 = __float2bfloat16_rn(w11);

    g_wfh[m][i] = make_uint2(pack_bf(w00, w01), pack_bf(w10, w11));
    g_wfl[m][i] = make_uint2(
        pack_bf(w00 - __bfloat162float(h00), w01 - __bfloat162float(h01)),
        pack_bf(w10 - __bfloat162float(h10), w11 - __bfloat162float(h11)));
}

// ---------------------------------------------------------------------------
// mma.sync GEMM: D[128 rows, 128 cols] = A @ W, bf16x3 split, fp32 accum.
// Warp tile 16x128, processed as two sequential 16x64 halves (acc = 32 regs)
// so 3 CTAs/SM fit in the register file. B fragments rolling-prefetched.
//   a_is_t=0: A = x split;  a_is_t=1: A = t split (LN2 output)
// qkv mode (is_out=0): blockIdx.y selects Wq/Wk/Wv -> g_Q/K/V
// out mode (is_out=1): W = Wo, out = g_h + relu(D + bo)
// ---------------------------------------------------------------------------
__global__ void __launch_bounds__(256, 3)
mma_gemm(int a_is_t, int w_base, const float* __restrict__ b0,
         const float* __restrict__ b1, const float* __restrict__ b2,
         float* __restrict__ dout, int is_out) {
    extern __shared__ char smem[];
    // A tiles: 128 rows x 136 bf16 stride (272B rows -> conflict-free ldmatrix)
    const int A_STRIDE_B = 272;
    const int OFF_LO = 128 * A_STRIDE_B;   // 34816
    int t = threadIdx.x, warp = t >> 5, lane = t & 31;
    int sel = blockIdx.y;
    int row0 = blockIdx.x * 128;

    const unsigned int* __restrict__ Ahi = a_is_t ? g_thi : g_xhi;
    const unsigned int* __restrict__ Alo = a_is_t ? g_tlo : g_xlo;
    const uint2* __restrict__ wfh = g_wfh[w_base + sel];
    const uint2* __restrict__ wfl = g_wfl[w_base + sel];
    const float* bias = is_out ? b0 : (sel == 0 ? b0 : sel == 1 ? b1 : b2);
    float* outp = is_out ? dout : (sel == 0 ? g_Q : sel == 1 ? g_K : g_V);

    // fill A hi/lo smem tiles
    for (int i = t; i < 8192; i += 256) {
        int row = i >> 6, p = i & 63;
        int grow = row0 + row;
        unsigned int vh = 0, vl = 0;
        if (grow < NN) { vh = Ahi[grow * 64 + p]; vl = Alo[grow * 64 + p]; }
        int off = row * A_STRIDE_B + p * 4;
        *reinterpret_cast<unsigned int*>(smem + off)          = vh;
        *reinterpret_cast<unsigned int*>(smem + OFF_LO + off) = vl;
    }
    __syncthreads();

    // ldmatrix source address for this lane
    int rowsel = (lane & 7) | (((lane >> 3) & 1) << 3);  // 0..15
    int colblk = lane >> 4;                              // 0/1 -> k +0/+8
    unsigned int sb = smem_u32(smem);
    unsigned int a_addr = sb + (warp * 16 + rowsel) * A_STRIDE_B + colblk * 16;

    int g = lane >> 2, tig = lane & 3;
    int r_lo = row0 + warp * 16 + g;
    int r_hi = r_lo + 8;

#pragma unroll 1
    for (int half = 0; half < 2; half++) {
        float acc[8][4];
#pragma unroll
        for (int nn = 0; nn < 8; nn++)
#pragma unroll
            for (int c = 0; c < 4; c++) acc[nn][c] = 0.f;

#pragma unroll 1
        for (int kk = 0; kk < 8; kk++) {
            unsigned int a_hi[4], a_lo[4];
            LDMATRIX_X4(a_hi, a_addr + kk * 32);
            LDMATRIX_X4(a_lo, a_addr + OFF_LO + kk * 32);
            const uint2* wh = wfh + (kk * 16 + half * 8) * 32 + lane;
            const uint2* wl = wfl + (kk * 16 + half * 8) * 32 + lane;
            uint2 bh = __ldg(wh);
            uint2 bl = __ldg(wl);
#pragma unroll
            for (int nn = 0; nn < 8; nn++) {
                uint2 nbh, nbl;
                if (nn < 7) {
                    nbh = __ldg(wh + (nn + 1) * 32);
                    nbl = __ldg(wl + (nn + 1) * 32);
                }
                MMA_BF16(acc[nn], a_hi, bh.x, bh.y);
                MMA_BF16(acc[nn], a_hi, bl.x, bl.y);
                MMA_BF16(acc[nn], a_lo, bh.x, bh.y);
                bh = nbh; bl = nbl;
            }
        }

        // epilogue for this half: lane g holds rows g/g+8, cols 2tig..2tig+1
#pragma unroll
        for (int nn = 0; nn < 8; nn++) {
            int col = (half * 8 + nn) * 8 + 2 * tig;
            float2 bb = *reinterpret_cast<const float2*>(bias + col);
            if (r_lo < NN) {
                float2 o;
                if (is_out) {
                    float2 hv = *reinterpret_cast<const float2*>(g_h + (size_t)r_lo * DD + col);
                    o.x = hv.x + fmaxf(acc[nn][0] + bb.x, 0.f);
                    o.y = hv.y + fmaxf(acc[nn][1] + bb.y, 0.f);
                } else {
                    o.x = acc[nn][0] + bb.x;
                    o.y = acc[nn][1] + bb.y;
                }
                *reinterpret_cast<float2*>(outp + (size_t)r_lo * DD + col) = o;
            }
            if (r_hi < NN) {
                float2 o;
                if (is_out) {
                    float2 hv = *reinterpret_cast<const float2*>(g_h + (size_t)r_hi * DD + col);
                    o.x = hv.x + fmaxf(acc[nn][2] + bb.x, 0.f);
                    o.y = hv.y + fmaxf(acc[nn][3] + bb.y, 0.f);
                } else {
                    o.x = acc[nn][2] + bb.x;
                    o.y = acc[nn][3] + bb.y;
                }
                *reinterpret_cast<float2*>(outp + (size_t)r_hi * DD + col) = o;
            }
        }
    }
}

// ---------------------------------------------------------------------------
// Edge kernel: one warp per edge
// ---------------------------------------------------------------------------
__global__ void edge_kernel(const int* __restrict__ src, const int* __restrict__ dst) {
    int warp = (blockIdx.x * blockDim.x + threadIdx.x) >> 5;
    int lane = threadIdx.x & 31;
    if (warp >= EE) return;

    int s = __ldg(src + warp);
    int d = __ldg(dst + warp);

    float4 kv = reinterpret_cast<const float4*>(g_K + (size_t)s * DD)[lane];
    float4 qv = reinterpret_cast<const float4*>(g_Q + (size_t)d * DD)[lane];
    float4 vv = reinterpret_cast<const float4*>(g_V + (size_t)s * DD)[lane];

    float p = kv.x * qv.x + kv.y * qv.y + kv.z * qv.z + kv.w * qv.w;
    p += __shfl_xor_sync(0xffffffffu, p, 1);
    p += __shfl_xor_sync(0xffffffffu, p, 2);

    float sc = __expf(fminf(fmaxf(p * 0.25f, -5.f), 5.f));

    float4* wptr = reinterpret_cast<float4*>(g_wV + (size_t)d * DD) + lane;
    asm volatile("red.global.add.v4.f32 [%0], {%1, %2, %3, %4};"
                 :: "l"(wptr), "f"(vv.x * sc), "f"(vv.y * sc),
                    "f"(vv.z * sc), "f"(vv.w * sc)
                 : "memory");
    if ((lane & 3) == 0)
        atomicAdd(g_z + (size_t)d * HH + (lane >> 2), sc);
}

// ---------------------------------------------------------------------------
// Norm kernel: attn normalize + LN1 -> g_h, LN2 -> bf16 split (g_thi/g_tlo)
// ---------------------------------------------------------------------------
__global__ void norm_kernel(const float* __restrict__ x,
                            const float* __restrict__ gamma1, const float* __restrict__ beta1,
                            const float* __restrict__ gamma2, const float* __restrict__ beta2) {
    int node = (blockIdx.x * blockDim.x + threadIdx.x) >> 5;
    int lane = threadIdx.x & 31;
    if (node >= NN) return;

    float4 xv = reinterpret_cast<const float4*>(x + (size_t)node * DD)[lane];
    float4 wv = reinterpret_cast<const float4*>(g_wV + (size_t)node * DD)[lane];
    float rz = 1.f / (g_z[(size_t)node * HH + (lane >> 2)] + 1e-3f);

    float4 y;
    y.x = xv.x + wv.x * rz;
    y.y = xv.y + wv.y * rz;
    y.z = xv.z + wv.z * rz;
    y.w = xv.w + wv.w * rz;

    float s  = y.x + y.y + y.z + y.w;
    float sq = y.x * y.x + y.y * y.y + y.z * y.z + y.w * y.w;
#pragma unroll
    for (int o = 16; o > 0; o >>= 1) {
        s  += __shfl_xor_sync(0xffffffffu, s,  o);
        sq += __shfl_xor_sync(0xffffffffu, sq, o);
    }
    float mu  = s * (1.f / DD);
    float var = sq * (1.f / DD) - mu * mu;
    float inv = rsqrtf(var + 1e-5f);

    float4 g1 = reinterpret_cast<const float4*>(gamma1)[lane];
    float4 b1 = reinterpret_cast<const float4*>(beta1)[lane];
    float4 h;
    h.x = (y.x - mu) * inv * g1.x + b1.x;
    h.y = (y.y - mu) * inv * g1.y + b1.y;
    h.z = (y.z - mu) * inv * g1.z + b1.z;
    h.w = (y.w - mu) * inv * g1.w + b1.w;
    reinterpret_cast<float4*>(g_h + (size_t)node * DD)[lane] = h;

    float s2  = h.x + h.y + h.z + h.w;
    float sq2 = h.x * h.x + h.y * h.y + h.z * h.z + h.w * h.w;
#pragma unroll
    for (int o = 16; o > 0; o >>= 1) {
        s2  += __shfl_xor_sync(0xffffffffu, s2,  o);
        sq2 += __shfl_xor_sync(0xffffffffu, sq2, o);
    }
    float mu2  = s2 * (1.f / DD);
    float var2 = sq2 * (1.f / DD) - mu2 * mu2;
    float inv2 = rsqrtf(var2 + 1e-5f);

    float4 g2 = reinterpret_cast<const float4*>(gamma2)[lane];
    float4 b2 = reinterpret_cast<const float4*>(beta2)[lane];
    float4 tt;
    tt.x = (h.x - mu2) * inv2 * g2.x + b2.x;
    tt.y = (h.y - mu2) * inv2 * g2.y + b2.y;
    tt.z = (h.z - mu2) * inv2 * g2.z + b2.z;
    tt.w = (h.w - mu2) * inv2 * g2.w + b2.w;

    __nv_bfloat162 h01 = __floats2bfloat162_rn(tt.x, tt.y);
    __nv_bfloat162 h23 = __floats2bfloat162_rn(tt.z, tt.w);
    float l0 = tt.x - __bfloat162float(h01.x);
    float l1 = tt.y - __bfloat162float(h01.y);
    float l2 = tt.z - __bfloat162float(h23.x);
    float l3 = tt.w - __bfloat162float(h23.y);
    int base = node * 64 + lane * 2;
    g_thi[base]     = *reinterpret_cast<unsigned int*>(&h01);
    g_thi[base + 1] = *reinterpret_cast<unsigned int*>(&h23);
    g_tlo[base]     = pack_bf(l0, l1);
    g_tlo[base + 1] = pack_bf(l2, l3);
}

// ---------------------------------------------------------------------------
extern "C" void kernel_launch(void* const* d_in, const int* in_sizes, int n_in,
                              void* d_out, int out_size) {
    const float* x      = (const float*)d_in[0];
    const int*   src    = (const int*)  d_in[1];
    const int*   dst    = (const int*)  d_in[2];
    const float* Wq     = (const float*)d_in[3];
    const float* bq     = (const float*)d_in[4];
    const float* Wk     = (const float*)d_in[5];
    const float* bk     = (const float*)d_in[6];
    const float* Wv     = (const float*)d_in[7];
    const float* bv     = (const float*)d_in[8];
    const float* Wo     = (const float*)d_in[9];
    const float* bo     = (const float*)d_in[10];
    const float* gamma1 = (const float*)d_in[11];
    const float* beta1  = (const float*)d_in[12];
    const float* gamma2 = (const float*)d_in[13];
    const float* beta2  = (const float*)d_in[14];
    float* out = (float*)d_out;

    const int MMA_SMEM = 2 * 128 * 272;  // 69632 B
    cudaFuncSetAttribute(mma_gemm, cudaFuncAttributeMaxDynamicSharedMemorySize, MMA_SMEM);

    // zero accumulators
    zero_kernel<<<(NN * DD / 4 + 255) / 256, 256>>>();

    // bf16 splits + W fragment bake
    convert_x<<<(NN * 64 + 255) / 256, 256>>>(x);
    convert_w<<<dim3(16, 4), 256>>>(Wq, Wk, Wv, Wo);

    // QKV projections (mma.sync bf16x3); A = x split (selected in-kernel)
    dim3 qkv_grid((NN + 127) / 128, 3);
    mma_gemm<<<qkv_grid, 256, MMA_SMEM>>>(0, 0, bq, bk, bv, nullptr, 0);

    // edge scores + scatter
    edge_kernel<<<EE / 8, 256>>>(src, dst);

    // attn normalize + LN1 + LN2(+split)
    norm_kernel<<<(NN + 7) / 8, 256>>>(x, gamma1, beta1, gamma2, beta2);

    // output projection + relu + residual; A = t split (selected in-kernel)
    mma_gemm<<<dim3((NN + 127) / 128, 1), 256, MMA_SMEM>>>(1, 3, bo, bo, bo, out, 1);
}

// round 10
// speedup vs baseline: 1.4325x; 1.0779x over previous
#include <cuda_runtime.h>
#include <cuda_bf16.h>
#include <math.h>
#include <stdint.h>

#define NN 50000
#define EE 800000
#define DD 128
#define HH 8

// ---------------- scratch (static device arrays, no allocation) -------------
__device__ float g_Q[NN * DD];
__device__ float g_K[NN * DD];
__device__ float g_V[NN * DD];
__device__ float g_wV[NN * DD];
__device__ float g_z[NN * HH];
__device__ float g_h[NN * DD];
// bf16 hi/lo splits of activations, packed bf16x2 (pair p = cols 2p, 2p+1)
__device__ unsigned int g_xhi[NN * 64];
__device__ unsigned int g_xlo[NN * 64];
__device__ unsigned int g_thi[NN * 64];
__device__ unsigned int g_tlo[NN * 64];
// W pre-baked into m16n8k16 B-fragment layout: [matrix][(kk*16+nn)*32 + lane]
__device__ uint2 g_wfh[4][4096];
__device__ uint2 g_wfl[4][4096];

// ---------------- helpers ---------------------------------------------------
__device__ __forceinline__ unsigned int smem_u32(const void* p) {
    unsigned int a;
    asm("{ .reg .u64 t; cvta.to.shared.u64 t, %1; cvt.u32.u64 %0, t; }" : "=r"(a) : "l"(p));
    return a;
}

__device__ __forceinline__ unsigned int pack_bf(float a, float b) {
    __nv_bfloat162 t = __floats2bfloat162_rn(a, b);
    return *reinterpret_cast<unsigned int*>(&t);
}

#define MMA_BF16(c, a, b0v, b1v)                                               \
    asm volatile("mma.sync.aligned.m16n8k16.row.col.f32.bf16.bf16.f32 "        \
                 "{%0,%1,%2,%3}, {%4,%5,%6,%7}, {%8,%9}, {%0,%1,%2,%3};"       \
                 : "+f"((c)[0]), "+f"((c)[1]), "+f"((c)[2]), "+f"((c)[3])      \
                 : "r"((a)[0]), "r"((a)[1]), "r"((a)[2]), "r"((a)[3]),         \
                   "r"(b0v), "r"(b1v))

#define LDMATRIX_X4(r, addr)                                                   \
    asm volatile("ldmatrix.sync.aligned.m8n8.x4.shared.b16 {%0,%1,%2,%3}, [%4];" \
                 : "=r"((r)[0]), "=r"((r)[1]), "=r"((r)[2]), "=r"((r)[3])      \
                 : "r"(addr))

// ---------------------------------------------------------------------------
// Zero accumulators
// ---------------------------------------------------------------------------
__global__ void zero_kernel() {
    int idx = blockIdx.x * 256 + threadIdx.x;
    float4 zf = make_float4(0.f, 0.f, 0.f, 0.f);
    if (idx < NN * DD / 4) reinterpret_cast<float4*>(g_wV)[idx] = zf;
    if (idx < NN * HH)     g_z[idx] = 0.f;
}

// ---------------------------------------------------------------------------
// Convert x -> bf16 hi/lo pairs
// ---------------------------------------------------------------------------
__global__ void convert_x(const float* __restrict__ x) {
    int i = blockIdx.x * 256 + threadIdx.x;
    if (i >= NN * 64) return;
    float2 v = reinterpret_cast<const float2*>(x)[i];
    __nv_bfloat162 hp = __floats2bfloat162_rn(v.x, v.y);
    float l0 = v.x - __bfloat162float(hp.x);
    float l1 = v.y - __bfloat162float(hp.y);
    g_xhi[i] = *reinterpret_cast<unsigned int*>(&hp);
    g_xlo[i] = pack_bf(l0, l1);
}

// ---------------------------------------------------------------------------
// Bake W (4 matrices) into mma.sync B-fragment layout (hi + lo splits).
// ---------------------------------------------------------------------------
__global__ void convert_w(const float* __restrict__ Wq, const float* __restrict__ Wk,
                          const float* __restrict__ Wv, const float* __restrict__ Wo) {
    int m = blockIdx.y;
    const float* W = (m == 0) ? Wq : (m == 1) ? Wk : (m == 2) ? Wv : Wo;
    int i = blockIdx.x * 256 + threadIdx.x;
    if (i >= 4096) return;
    int lane = i & 31, nn = (i >> 5) & 15, kk = i >> 9;
    int g = lane >> 2, tig = lane & 3;
    int k0 = kk * 16 + 2 * tig;
    int col = nn * 8 + g;

    float w00 = W[(k0)     * 128 + col];
    float w01 = W[(k0 + 1) * 128 + col];
    float w10 = W[(k0 + 8) * 128 + col];
    float w11 = W[(k0 + 9) * 128 + col];

    __nv_bfloat16 h00 = __float2bfloat16_rn(w00);
    __nv_bfloat16 h01 = __float2bfloat16_rn(w01);
    __nv_bfloat16 h10 = __float2bfloat16_rn(w10);
    __nv_bfloat16 h11 = __float2bfloat16_rn(w11);

    g_wfh[m][i] = make_uint2(pack_bf(w00, w01), pack_bf(w10, w11));
    g_wfl[m][i] = make_uint2(
        pack_bf(w00 - __bfloat162float(h00), w01 - __bfloat162float(h01)),
        pack_bf(w10 - __bfloat162float(h10), w11 - __bfloat162float(h11)));
}

// ---------------------------------------------------------------------------
// mma.sync GEMM: D[128 rows, 128 cols] = A @ W, bf16x3 split, fp32 accum.
// Warp tile 16x128 as two sequential 16x64 halves; each half processed as
// two nn-groups of 4 with term-major MMA order (distance-4 accumulator
// chains keep the tensor pipe streaming) and rolling B-fragment prefetch.
//   a_is_t=0: A = x split;  a_is_t=1: A = t split (LN2 output)
// qkv mode (is_out=0): blockIdx.y selects Wq/Wk/Wv -> g_Q/K/V
// out mode (is_out=1): W = Wo, out = g_h + relu(D + bo)
// ---------------------------------------------------------------------------
__global__ void __launch_bounds__(256, 3)
mma_gemm(int a_is_t, int w_base, const float* __restrict__ b0,
         const float* __restrict__ b1, const float* __restrict__ b2,
         float* __restrict__ dout, int is_out) {
    extern __shared__ char smem[];
    // A tiles: 128 rows x 136 bf16 stride (272B rows -> conflict-free ldmatrix)
    const int A_STRIDE_B = 272;
    const int OFF_LO = 128 * A_STRIDE_B;   // 34816
    int t = threadIdx.x, warp = t >> 5, lane = t & 31;
    int sel = blockIdx.y;
    int row0 = blockIdx.x * 128;

    const unsigned int* __restrict__ Ahi = a_is_t ? g_thi : g_xhi;
    const unsigned int* __restrict__ Alo = a_is_t ? g_tlo : g_xlo;
    const uint2* __restrict__ wfh = g_wfh[w_base + sel];
    const uint2* __restrict__ wfl = g_wfl[w_base + sel];
    const float* bias = is_out ? b0 : (sel == 0 ? b0 : sel == 1 ? b1 : b2);
    float* outp = is_out ? dout : (sel == 0 ? g_Q : sel == 1 ? g_K : g_V);

    // fill A hi/lo smem tiles
    for (int i = t; i < 8192; i += 256) {
        int row = i >> 6, p = i & 63;
        int grow = row0 + row;
        unsigned int vh = 0, vl = 0;
        if (grow < NN) { vh = Ahi[grow * 64 + p]; vl = Alo[grow * 64 + p]; }
        int off = row * A_STRIDE_B + p * 4;
        *reinterpret_cast<unsigned int*>(smem + off)          = vh;
        *reinterpret_cast<unsigned int*>(smem + OFF_LO + off) = vl;
    }
    __syncthreads();

    // ldmatrix source address for this lane
    int rowsel = (lane & 7) | (((lane >> 3) & 1) << 3);  // 0..15
    int colblk = lane >> 4;                              // 0/1 -> k +0/+8
    unsigned int sb = smem_u32(smem);
    unsigned int a_addr = sb + (warp * 16 + rowsel) * A_STRIDE_B + colblk * 16;

    int g = lane >> 2, tig = lane & 3;
    int r_lo = row0 + warp * 16 + g;
    int r_hi = r_lo + 8;

#pragma unroll 1
    for (int half = 0; half < 2; half++) {
        // fragment index for (kk, nn): (kk*16 + half*8 + nn)*32 + lane
        const uint2* bh_base = wfh + half * 8 * 32 + lane;
        const uint2* bl_base = wfl + half * 8 * 32 + lane;

        float acc[8][4];
#pragma unroll
        for (int nn = 0; nn < 8; nn++)
#pragma unroll
            for (int c = 0; c < 4; c++) acc[nn][c] = 0.f;

        // preload G0 fragments for kk=0
        uint2 bhA[4], blA[4];
#pragma unroll
        for (int i = 0; i < 4; i++) {
            bhA[i] = __ldg(bh_base + i * 32);
            blA[i] = __ldg(bl_base + i * 32);
        }

#pragma unroll 1
        for (int kk = 0; kk < 8; kk++) {
            unsigned int a_hi[4], a_lo[4];
            LDMATRIX_X4(a_hi, a_addr + kk * 32);
            LDMATRIX_X4(a_lo, a_addr + OFF_LO + kk * 32);

            // prefetch G1 (nn 4..7) of this kk
            uint2 bhB[4], blB[4];
#pragma unroll
            for (int i = 0; i < 4; i++) {
                bhB[i] = __ldg(bh_base + (kk * 16 + 4 + i) * 32);
                blB[i] = __ldg(bl_base + (kk * 16 + 4 + i) * 32);
            }

            // G0: term-major, distance-4 accumulator chains
#pragma unroll
            for (int i = 0; i < 4; i++) MMA_BF16(acc[i], a_hi, bhA[i].x, bhA[i].y);
#pragma unroll
            for (int i = 0; i < 4; i++) MMA_BF16(acc[i], a_hi, blA[i].x, blA[i].y);
#pragma unroll
            for (int i = 0; i < 4; i++) MMA_BF16(acc[i], a_lo, bhA[i].x, bhA[i].y);

            // prefetch G0 of next kk
            if (kk < 7) {
#pragma unroll
                for (int i = 0; i < 4; i++) {
                    bhA[i] = __ldg(bh_base + ((kk + 1) * 16 + i) * 32);
                    blA[i] = __ldg(bl_base + ((kk + 1) * 16 + i) * 32);
                }
            }

            // G1
#pragma unroll
            for (int i = 0; i < 4; i++) MMA_BF16(acc[4 + i], a_hi, bhB[i].x, bhB[i].y);
#pragma unroll
            for (int i = 0; i < 4; i++) MMA_BF16(acc[4 + i], a_hi, blB[i].x, blB[i].y);
#pragma unroll
            for (int i = 0; i < 4; i++) MMA_BF16(acc[4 + i], a_lo, bhB[i].x, bhB[i].y);
        }

        // epilogue for this half: lane g holds rows g/g+8, cols 2tig..2tig+1
#pragma unroll
        for (int nn = 0; nn < 8; nn++) {
            int col = (half * 8 + nn) * 8 + 2 * tig;
            float2 bb = *reinterpret_cast<const float2*>(bias + col);
            if (r_lo < NN) {
                float2 o;
                if (is_out) {
                    float2 hv = *reinterpret_cast<const float2*>(g_h + (size_t)r_lo * DD + col);
                    o.x = hv.x + fmaxf(acc[nn][0] + bb.x, 0.f);
                    o.y = hv.y + fmaxf(acc[nn][1] + bb.y, 0.f);
                } else {
                    o.x = acc[nn][0] + bb.x;
                    o.y = acc[nn][1] + bb.y;
                }
                *reinterpret_cast<float2*>(outp + (size_t)r_lo * DD + col) = o;
            }
            if (r_hi < NN) {
                float2 o;
                if (is_out) {
                    float2 hv = *reinterpret_cast<const float2*>(g_h + (size_t)r_hi * DD + col);
                    o.x = hv.x + fmaxf(acc[nn][2] + bb.x, 0.f);
                    o.y = hv.y + fmaxf(acc[nn][3] + bb.y, 0.f);
                } else {
                    o.x = acc[nn][2] + bb.x;
                    o.y = acc[nn][3] + bb.y;
                }
                *reinterpret_cast<float2*>(outp + (size_t)r_hi * DD + col) = o;
            }
        }
    }
}

// ---------------------------------------------------------------------------
// Edge kernel: one warp per edge
// ---------------------------------------------------------------------------
__global__ void edge_kernel(const int* __restrict__ src, const int* __restrict__ dst) {
    int warp = (blockIdx.x * blockDim.x + threadIdx.x) >> 5;
    int lane = threadIdx.x & 31;
    if (warp >= EE) return;

    int s = __ldg(src + warp);
    int d = __ldg(dst + warp);

    float4 kv = reinterpret_cast<const float4*>(g_K + (size_t)s * DD)[lane];
    float4 qv = reinterpret_cast<const float4*>(g_Q + (size_t)d * DD)[lane];
    float4 vv = reinterpret_cast<const float4*>(g_V + (size_t)s * DD)[lane];

    float p = kv.x * qv.x + kv.y * qv.y + kv.z * qv.z + kv.w * qv.w;
    p += __shfl_xor_sync(0xffffffffu, p, 1);
    p += __shfl_xor_sync(0xffffffffu, p, 2);

    float sc = __expf(fminf(fmaxf(p * 0.25f, -5.f), 5.f));

    float4* wptr = reinterpret_cast<float4*>(g_wV + (size_t)d * DD) + lane;
    asm volatile("red.global.add.v4.f32 [%0], {%1, %2, %3, %4};"
                 :: "l"(wptr), "f"(vv.x * sc), "f"(vv.y * sc),
                    "f"(vv.z * sc), "f"(vv.w * sc)
                 : "memory");
    if ((lane & 3) == 0)
        atomicAdd(g_z + (size_t)d * HH + (lane >> 2), sc);
}

// ---------------------------------------------------------------------------
// Norm kernel: attn normalize + LN1 -> g_h, LN2 -> bf16 split (g_thi/g_tlo)
// ---------------------------------------------------------------------------
__global__ void norm_kernel(const float* __restrict__ x,
                            const float* __restrict__ gamma1, const float* __restrict__ beta1,
                            const float* __restrict__ gamma2, const float* __restrict__ beta2) {
    int node = (blockIdx.x * blockDim.x + threadIdx.x) >> 5;
    int lane = threadIdx.x & 31;
    if (node >= NN) return;

    float4 xv = reinterpret_cast<const float4*>(x + (size_t)node * DD)[lane];
    float4 wv = reinterpret_cast<const float4*>(g_wV + (size_t)node * DD)[lane];
    float rz = 1.f / (g_z[(size_t)node * HH + (lane >> 2)] + 1e-3f);

    float4 y;
    y.x = xv.x + wv.x * rz;
    y.y = xv.y + wv.y * rz;
    y.z = xv.z + wv.z * rz;
    y.w = xv.w + wv.w * rz;

    float s  = y.x + y.y + y.z + y.w;
    float sq = y.x * y.x + y.y * y.y + y.z * y.z + y.w * y.w;
#pragma unroll
    for (int o = 16; o > 0; o >>= 1) {
        s  += __shfl_xor_sync(0xffffffffu, s,  o);
        sq += __shfl_xor_sync(0xffffffffu, sq, o);
    }
    float mu  = s * (1.f / DD);
    float var = sq * (1.f / DD) - mu * mu;
    float inv = rsqrtf(var + 1e-5f);

    float4 g1 = reinterpret_cast<const float4*>(gamma1)[lane];
    float4 b1 = reinterpret_cast<const float4*>(beta1)[lane];
    float4 h;
    h.x = (y.x - mu) * inv * g1.x + b1.x;
    h.y = (y.y - mu) * inv * g1.y + b1.y;
    h.z = (y.z - mu) * inv * g1.z + b1.z;
    h.w = (y.w - mu) * inv * g1.w + b1.w;
    reinterpret_cast<float4*>(g_h + (size_t)node * DD)[lane] = h;

    float s2  = h.x + h.y + h.z + h.w;
    float sq2 = h.x * h.x + h.y * h.y + h.z * h.z + h.w * h.w;
#pragma unroll
    for (int o = 16; o > 0; o >>= 1) {
        s2  += __shfl_xor_sync(0xffffffffu, s2,  o);
        sq2 += __shfl_xor_sync(0xffffffffu, sq2, o);
    }
    float mu2  = s2 * (1.f / DD);
    float var2 = sq2 * (1.f / DD) - mu2 * mu2;
    float inv2 = rsqrtf(var2 + 1e-5f);

    float4 g2 = reinterpret_cast<const float4*>(gamma2)[lane];
    float4 b2 = reinterpret_cast<const float4*>(beta2)[lane];
    float4 tt;
    tt.x = (h.x - mu2) * inv2 * g2.x + b2.x;
    tt.y = (h.y - mu2) * inv2 * g2.y + b2.y;
    tt.z = (h.z - mu2) * inv2 * g2.z + b2.z;
    tt.w = (h.w - mu2) * inv2 * g2.w + b2.w;

    __nv_bfloat162 h01 = __floats2bfloat162_rn(tt.x, tt.y);
    __nv_bfloat162 h23 = __floats2bfloat162_rn(tt.z, tt.w);
    float l0 = tt.x - __bfloat162float(h01.x);
    float l1 = tt.y - __bfloat162float(h01.y);
    float l2 = tt.z - __bfloat162float(h23.x);
    float l3 = tt.w - __bfloat162float(h23.y);
    int base = node * 64 + lane * 2;
    g_thi[base]     = *reinterpret_cast<unsigned int*>(&h01);
    g_thi[base + 1] = *reinterpret_cast<unsigned int*>(&h23);
    g_tlo[base]     = pack_bf(l0, l1);
    g_tlo[base + 1] = pack_bf(l2, l3);
}

// ---------------------------------------------------------------------------
extern "C" void kernel_launch(void* const* d_in, const int* in_sizes, int n_in,
                              void* d_out, int out_size) {
    const float* x      = (const float*)d_in[0];
    const int*   src    = (const int*)  d_in[1];
    const int*   dst    = (const int*)  d_in[2];
    const float* Wq     = (const float*)d_in[3];
    const float* bq     = (const float*)d_in[4];
    const float* Wk     = (const float*)d_in[5];
    const float* bk     = (const float*)d_in[6];
    const float* Wv     = (const float*)d_in[7];
    const float* bv     = (const float*)d_in[8];
    const float* Wo     = (const float*)d_in[9];
    const float* bo     = (const float*)d_in[10];
    const float* gamma1 = (const float*)d_in[11];
    const float* beta1  = (const float*)d_in[12];
    const float* gamma2 = (const float*)d_in[13];
    const float* beta2  = (const float*)d_in[14];
    float* out = (float*)d_out;

    const int MMA_SMEM = 2 * 128 * 272;  // 69632 B
    cudaFuncSetAttribute(mma_gemm, cudaFuncAttributeMaxDynamicSharedMemorySize, MMA_SMEM);

    // zero accumulators
    zero_kernel<<<(NN * DD / 4 + 255) / 256, 256>>>();

    // bf16 splits + W fragment bake
    convert_x<<<(NN * 64 + 255) / 256, 256>>>(x);
    convert_w<<<dim3(16, 4), 256>>>(Wq, Wk, Wv, Wo);

    // QKV projections (mma.sync bf16x3); A = x split (selected in-kernel)
    dim3 qkv_grid((NN + 127) / 128, 3);
    mma_gemm<<<qkv_grid, 256, MMA_SMEM>>>(0, 0, bq, bk, bv, nullptr, 0);

    // edge scores + scatter
    edge_kernel<<<EE / 8, 256>>>(src, dst);

    // attn normalize + LN1 + LN2(+split)
    norm_kernel<<<(NN + 7) / 8, 256>>>(x, gamma1, beta1, gamma2, beta2);

    // output projection + relu + residual; A = t split (selected in-kernel)
    mma_gemm<<<dim3((NN + 127) / 128, 1), 256, MMA_SMEM>>>(1, 3, bo, bo, bo, out, 1);
}